// round 12
// baseline (speedup 1.0000x reference)
#include <cuda_runtime.h>

// out[b, t, f] = (t == (int)((1.0f - x[b,f]) * 100.0f)) ? 1.0f : 0.0f
// B=2048, T=100, F=1024. Output 839 MB -> pure HBM-store-bound.
// R12: R11 structure (TCHUNK=2, 2D grid t-fastest, 102400 blocks), store
//      policy probe: __stcs -> __stwt (write-through, skip L2 dirty-line
//      bookkeeping). History: 25:120.8 / 10:120.9 / 5:114.7 / 4:114.6 /
//      2(.cs):113.1 / 1:127.0.

#define B 2048
#define T 100
#define TCHUNK 2
#define NCHUNK (T / TCHUNK)   // 50
#define F 1024
#define F4 (F / 4)            // 256

__global__ __launch_bounds__(256, 8)
void spike_latency_kernel(const float4* __restrict__ x, float4* __restrict__ out) {
    int t0 = blockIdx.x * TCHUNK;        // t-chunk: fastest-varying -> dense wave
    int b  = blockIdx.y;                 // batch row
    int f4 = threadIdx.x;                // 0 .. 255

    float4 xv = __ldg(x + (size_t)b * F4 + f4);
    int s0 = (int)((1.0f - xv.x) * 100.0f);
    int s1 = (int)((1.0f - xv.y) * 100.0f);
    int s2 = (int)((1.0f - xv.z) * 100.0f);
    int s3 = (int)((1.0f - xv.w) * 100.0f);

    float4* po = out + (size_t)b * (T * F4) + (size_t)t0 * F4 + f4;

#pragma unroll
    for (int i = 0; i < TCHUNK; i++) {
        int t = t0 + i;
        float4 v;
        v.x = (t == s0) ? 1.0f : 0.0f;
        v.y = (t == s1) ? 1.0f : 0.0f;
        v.z = (t == s2) ? 1.0f : 0.0f;
        v.w = (t == s3) ? 1.0f : 0.0f;
        __stwt(po + (size_t)i * F4, v);   // write-through streaming store
    }
}

extern "C" void kernel_launch(void* const* d_in, const int* in_sizes, int n_in,
                              void* d_out, int out_size) {
    const float4* x = (const float4*)d_in[0];
    float4* out = (float4*)d_out;
    dim3 grid(NCHUNK, B);                // (50, 2048) = 102400 blocks
    spike_latency_kernel<<<grid, 256>>>(x, out);
}

// round 13
// speedup vs baseline: 1.2729x; 1.2729x over previous
#include <cuda_runtime.h>

// out[b, t, f] = (t == (int)((1.0f - x[b,f]) * 100.0f)) ? 1.0f : 0.0f
// B=2048, T=100, F=1024. Output 839 MB -> pure HBM-store-bound.
// FINAL (R11 config): TCHUNK=2, 2D grid with t-chunk fastest-varying
// (dense ~24MB wave write footprint, x L2-resident), 128-bit evict-first
// streaming stores. 113.1 us = 7.43 TB/s = 93% of 8 TB/s HBM spec.
// Lever map: grain 25:120.8/10:120.9/5:114.7/4:114.6/2:113.1/1:127.0;
// v8 stores regress (131.6); .wt regresses (143.9); .cs ~= default.

#define B 2048
#define T 100
#define TCHUNK 2
#define NCHUNK (T / TCHUNK)   // 50
#define F 1024
#define F4 (F / 4)            // 256

__global__ __launch_bounds__(256, 8)
void spike_latency_kernel(const float4* __restrict__ x, float4* __restrict__ out) {
    int t0 = blockIdx.x * TCHUNK;        // t-chunk: fastest-varying -> dense wave
    int b  = blockIdx.y;                 // batch row
    int f4 = threadIdx.x;                // 0 .. 255

    float4 xv = __ldg(x + (size_t)b * F4 + f4);
    int s0 = (int)((1.0f - xv.x) * 100.0f);
    int s1 = (int)((1.0f - xv.y) * 100.0f);
    int s2 = (int)((1.0f - xv.z) * 100.0f);
    int s3 = (int)((1.0f - xv.w) * 100.0f);

    float4* po = out + (size_t)b * (T * F4) + (size_t)t0 * F4 + f4;

#pragma unroll
    for (int i = 0; i < TCHUNK; i++) {
        int t = t0 + i;
        float4 v;
        v.x = (t == s0) ? 1.0f : 0.0f;
        v.y = (t == s1) ? 1.0f : 0.0f;
        v.z = (t == s2) ? 1.0f : 0.0f;
        v.w = (t == s3) ? 1.0f : 0.0f;
        __stcs(po + (size_t)i * F4, v);   // evict-first streaming store
    }
}

extern "C" void kernel_launch(void* const* d_in, const int* in_sizes, int n_in,
                              void* d_out, int out_size) {
    const float4* x = (const float4*)d_in[0];
    float4* out = (float4*)d_out;
    dim3 grid(NCHUNK, B);                // (50, 2048) = 102400 blocks
    spike_latency_kernel<<<grid, 256>>>(x, out);
}